// round 17
// baseline (speedup 1.0000x reference)
#include <cuda_runtime.h>
#include <math.h>

// Depthwise 3D Gaussian blur (xi=2, K=13, pad=6) on (1,3,192,192,192) fp32.
// R16: WH kernel double-buffered over NT=8 d-plane tiles per CTA (cp.async
//      prefetch pipeline, 96KB dynamic smem, grid = exactly 1 wave of 288
//      CTAs at 2/SM) -> DRAM duty ~100%. D pass = R15 float1 (26.3us).

#define NN 192
#define RR 6
#define KK 13

#define WT   96     // w-tile (24 float4)
#define HT   96     // h outputs per CTA tile
#define RAWR 108    // raw rows incl +-6 h halo
#define RSTR 108    // raw row stride in floats (96 + 12 w halo)
#define HSEG 12     // h outputs per thread (8 h-groups)
#define LD2  54     // float2 per row
#define LDIT 31     // ceil(RAWR*LD2 / 192)
#define NT   8      // d-plane tiles per CTA
#define BUFSZ 12000 // floats per smem buffer (11664 data + overshoot pad)

constexpr int PLANE = NN * NN;          // 36864
constexpr int VOL   = NN * NN * NN;     // 7077888
constexpr long TOTAL = 3L * VOL;

// Scratch (allocation-free rule): one 85 MB temp.
__device__ __align__(16) float g_tmpA[TOTAL];

struct GW { float g[KK]; };

// Packed fp32x2 FMA (Blackwell f32x2 pipe).
__device__ __forceinline__ float2 ffma2(float2 a, float2 b, float2 c) {
    float2 r;
    asm("fma.rn.f32x2 %0, %1, %2, %3;"
        : "=l"(reinterpret_cast<unsigned long long&>(r))
        : "l"(reinterpret_cast<unsigned long long&>(a)),
          "l"(reinterpret_cast<unsigned long long&>(b)),
          "l"(reinterpret_cast<unsigned long long&>(c)));
    return r;
}

// 8-byte cp.async with runtime src-size (0 -> zero-fill, no global read).
__device__ __forceinline__ void cpasync8(unsigned saddr, const void* g, int sz) {
    asm volatile("cp.async.ca.shared.global [%0], [%1], 8, %2;"
                 :: "r"(saddr), "l"(g), "r"(sz) : "memory");
}

// ---------------- Kernel 1: fused W + H blur, pipelined over d -------------
// grid = (2 wchunks, 24 d0, 3c x 2 hchunks) = 288 CTAs, block = 192.
// Each CTA: 8 tiles at d = d0 + 24*t, double-buffered cp.async prefetch.
__global__ __launch_bounds__(192) void conv_wh_kernel(const float* __restrict__ in,
                                                      float* __restrict__ out, GW gw) {
    extern __shared__ __align__(16) float raw2[];   // 2 * BUFSZ floats

    const int c  = blockIdx.z >> 1;
    const int hc = blockIdx.z & 1;
    const int d0 = blockIdx.y;
    const int w0 = blockIdx.x * WT;
    const int h0 = hc * HT;
    const int tid = threadIdx.x;

    const unsigned sb = (unsigned)__cvta_generic_to_shared(raw2);
    const int tw = tid % 24;        // float4 slot in w (0..23)
    const int hg = tid / 24;        // 0..7
    const int hb = hg * HSEG;       // local output row base

    // Issue one tile's loads into buffer `buf` (31 fixed LDGSTS, zfill halo).
    auto issue_load = [&](int t, int buf) {
        const int d = d0 + 24 * t;
        const float* src = in + (c * NN + d) * PLANE;
        const unsigned sbase = sb + (unsigned)buf * (BUFSZ * 4u);
#pragma unroll
        for (int i = 0; i < LDIT; i++) {
            const int idx = tid + i * 192;         // < 5952
            const int h = idx / LD2;
            const int k = idx - h * LD2;
            const int gh = h0 + h - RR;
            const int gwp = w0 - RR + 2 * k;
            const bool ok = ((unsigned)gh < NN) && ((unsigned)gwp < NN);
            const float* g = src + (ok ? (gh * NN + gwp) : 0);
            cpasync8(sbase + (unsigned)(h * RSTR + 2 * k) * 4u, g, ok ? 8 : 0);
        }
        asm volatile("cp.async.commit_group;" ::: "memory");
    };

    issue_load(0, 0);

#pragma unroll 1
    for (int t = 0; t < NT; t++) {
        if (t + 1 < NT) {
            issue_load(t + 1, (t + 1) & 1);
            asm volatile("cp.async.wait_group 1;" ::: "memory");
        } else {
            asm volatile("cp.async.wait_group 0;" ::: "memory");
        }
        __syncthreads();   // all threads' tile-t copies visible

        const float* raw = raw2 + (t & 1) * BUFSZ;
        const int d = d0 + 24 * t;
        float* dst = out + (c * NN + d) * PLANE + (h0 + hb) * NN + w0 + 4 * tw;

        // W-blur of local raw row r at float4 slot tw, packed f32x2.
        auto wblur = [&](int r) -> float4 {
            const float* rp = raw + r * RSTR + 4 * tw;
            const float4 x0 = *(const float4*)(rp);
            const float4 x1 = *(const float4*)(rp + 4);
            const float4 x2 = *(const float4*)(rp + 8);
            const float4 x3 = *(const float4*)(rp + 12);
            const float2 e0 = make_float2(x0.x, x0.y), e1 = make_float2(x0.z, x0.w);
            const float2 e2 = make_float2(x1.x, x1.y), e3 = make_float2(x1.z, x1.w);
            const float2 e4 = make_float2(x2.x, x2.y), e5 = make_float2(x2.z, x2.w);
            const float2 e6 = make_float2(x3.x, x3.y), e7 = make_float2(x3.z, x3.w);
            const float2 p1  = make_float2(e0.y, e1.x);
            const float2 p3  = make_float2(e1.y, e2.x);
            const float2 p5  = make_float2(e2.y, e3.x);
            const float2 p7  = make_float2(e3.y, e4.x);
            const float2 p9  = make_float2(e4.y, e5.x);
            const float2 p11 = make_float2(e5.y, e6.x);
            const float2 p13 = make_float2(e6.y, e7.x);
            const float2 p[15] = {e0, p1, e1, p3, e2, p5, e3, p7,
                                  e4, p9, e5, p11, e6, p13, e7};
            float2 a01 = make_float2(0.f, 0.f);
            float2 a23 = make_float2(0.f, 0.f);
#pragma unroll
            for (int j = 0; j < KK; j++) {
                const float2 gj = make_float2(gw.g[j], gw.g[j]);
                a01 = ffma2(gj, p[j],     a01);
                a23 = ffma2(gj, p[j + 2], a23);
            }
            return make_float4(a01.x, a01.y, a23.x, a23.y);
        };

        // 13-deep sliding window of W-blurred rows (raw rows hb..hb+23).
        float4 win[KK];
#pragma unroll
        for (int j = 0; j < KK - 1; j++) win[j] = wblur(hb + j);

#pragma unroll
        for (int i = 0; i < HSEG; i++) {
            win[KK - 1] = wblur(hb + i + (KK - 1));

            float2 acc0 = make_float2(0.f, 0.f);
            float2 acc1 = make_float2(0.f, 0.f);
#pragma unroll
            for (int j = 0; j < KK; j++) {
                const float2 gj = make_float2(gw.g[j], gw.g[j]);
                acc0 = ffma2(gj, make_float2(win[j].x, win[j].y), acc0);
                acc1 = ffma2(gj, make_float2(win[j].z, win[j].w), acc1);
            }
            *(float4*)(dst + i * NN) = make_float4(acc0.x, acc0.y, acc1.x, acc1.y);

#pragma unroll
            for (int j = 0; j < KK - 1; j++) win[j] = win[j + 1];
        }

        __syncthreads();   // done reading buf[t&1] before load(t+2) overwrites
    }
}

// ---------------- Kernel 2: conv along D, float1 per thread (R15) ----------
__global__ __launch_bounds__(192) void conv_axis_kernel(const float* __restrict__ in,
                                                        float* __restrict__ out, GW gw) {
    const int o = blockIdx.y;                  // c*192 + h, < 576
    const int base = (o / NN) * VOL + (o % NN) * NN;
    const float* pin = in + base + threadIdx.x;
    float* pout = out + base + threadIdx.x;

    const int p0 = blockIdx.x * 48;

    float win[KK];

#pragma unroll
    for (int j = 0; j < KK - 1; j++) {
        const int q = p0 - RR + j;
        float v = 0.f;
        if (q >= 0 && q < NN) v = pin[q * PLANE];
        win[j] = v;
    }

#pragma unroll
    for (int i = 0; i < 48; i++) {
        const int p = p0 + i;
        const int q = p + RR;
        float v = 0.f;
        if (q < NN) v = pin[q * PLANE];
        win[KK - 1] = v;

        float acc = 0.f;
#pragma unroll
        for (int j = 0; j < KK; j++) acc = fmaf(gw.g[j], win[j], acc);
        pout[p * PLANE] = acc;

#pragma unroll
        for (int j = 0; j < KK - 1; j++) win[j] = win[j + 1];
    }
}

extern "C" void kernel_launch(void* const* d_in, const int* in_sizes, int n_in,
                              void* d_out, int out_size) {
    const float* x = (const float*)d_in[0];   // (1,3,192,192,192) fp32
    float* out = (float*)d_out;

    void* pA = nullptr;
    cudaGetSymbolAddress(&pA, g_tmpA);
    float* tA = (float*)pA;

    // Host-side weights (double precision, normalized Gaussian, xi=2).
    GW gw;
    {
        double v[KK], s = 0.0;
        for (int j = 0; j < KK; j++) {
            double dd = (double)(j - RR);
            v[j] = exp(-dd * dd / 8.0);
            s += v[j];
        }
        for (int j = 0; j < KK; j++) gw.g[j] = (float)(v[j] / s);
    }

    // Allow 96KB dynamic smem (idempotent; host-side, not a stream op).
    const int dynsmem = 2 * BUFSZ * sizeof(float);   // 96,000 B
    cudaFuncSetAttribute(conv_wh_kernel,
                         cudaFuncAttributeMaxDynamicSharedMemorySize, dynsmem);

    // Fused W+H blur: x -> tA. 288 CTAs (one wave at 2 CTAs/SM), NT=8 tiles.
    conv_wh_kernel<<<dim3(2, 24, 6), 192, dynsmem>>>(x, tA, gw);

    // D pass: tA -> out. float1 lanes across full W. grid (4, 576).
    conv_axis_kernel<<<dim3(4, 576), 192>>>(tA, out, gw);
}